// round 7
// baseline (speedup 1.0000x reference)
#include <cuda_runtime.h>
#include <cuda_fp16.h>
#include <stdint.h>

#define EMBED 1024
#define BATCH 4
#define SEQ   2048
#define MTOT  (BATCH * SEQ)   // 8192

#define BM 256
#define BN 128
#define BKH 32                 // fp16 k elements per stage
#define NTHREADS 512

#define ROWB   64              // bytes per SMEM row (XOR swizzle, no pad)
#define TILEA  (256 * ROWB)    // 16384 B (A hi or lo)
#define TILEBB (128 * ROWB)    // 8192 B  (B hi or lo)
#define OFF_AH 0
#define OFF_AL TILEA
#define OFF_BH (2 * TILEA)
#define OFF_BL (2 * TILEA + TILEBB)
#define STAGEB (2 * TILEA + 2 * TILEBB)  // 49152
#define NSTAGE 4
#define SMEM_DYN (NSTAGE * STAGEB)       // 196608

#define SWZB(row, c) ((c) ^ ((((row) >> 1) & 3) << 4))

// ---------------- scratch (device globals; fp16 split operands) ------------
__device__ __align__(128) __half g_xh[(size_t)MTOT * EMBED];
__device__ __align__(128) __half g_xl[(size_t)MTOT * EMBED];
__device__ __align__(128) __half g_Wh[(size_t)3 * EMBED * EMBED];
__device__ __align__(128) __half g_Wl[(size_t)3 * EMBED * EMBED];
__device__ __align__(128) __half g_Qh[(size_t)MTOT * EMBED];
__device__ __align__(128) __half g_Ql[(size_t)MTOT * EMBED];
__device__ __align__(128) __half g_Kh[(size_t)MTOT * EMBED];
__device__ __align__(128) __half g_Kl[(size_t)MTOT * EMBED];
__device__ __align__(128) __half g_Vth[(size_t)BATCH * EMBED * SEQ]; // [b][e][s]
__device__ __align__(128) __half g_Vtl[(size_t)BATCH * EMBED * SEQ];
__device__ __align__(128) __half g_wh[(size_t)BATCH * SEQ * SEQ];    // [b][q][k]
__device__ __align__(128) __half g_wl[(size_t)BATCH * SEQ * SEQ];

// ---------------------------------------------------------------------------
__device__ __forceinline__ uint32_t smem_u32(const void* p) {
    uint32_t a;
    asm("{ .reg .u64 t; cvta.to.shared.u64 t, %1; cvt.u32.u64 %0, t; }"
        : "=r"(a) : "l"(p));
    return a;
}

__device__ __forceinline__ void cp16(uint32_t saddr, const void* g) {
    asm volatile("cp.async.cg.shared.global [%0], [%1], 16;"
                 :: "r"(saddr), "l"(g));
}

#define LDSM4(r0, r1, r2, r3, addr)                                          \
    asm volatile("ldmatrix.sync.aligned.m8n8.x4.shared.b16 {%0,%1,%2,%3}, [%4];" \
                 : "=r"(r0), "=r"(r1), "=r"(r2), "=r"(r3) : "r"(addr))

#define MMA16816(d, a0, a1, a2, a3, b0, b1)                                  \
    asm volatile("mma.sync.aligned.m16n8k16.row.col.f32.f16.f16.f32 "        \
                 "{%0,%1,%2,%3}, {%4,%5,%6,%7}, {%8,%9}, {%0,%1,%2,%3};"     \
                 : "+f"(d[0]), "+f"(d[1]), "+f"(d[2]), "+f"(d[3])            \
                 : "r"(a0), "r"(a1), "r"(a2), "r"(a3), "r"(b0), "r"(b1))

__device__ __forceinline__ uint32_t packh(__half a, __half b) {
    return (uint32_t)__half_as_ushort(a) | ((uint32_t)__half_as_ushort(b) << 16);
}

__device__ __forceinline__ void split1(float v, __half& h, __half& l) {
    h = __float2half(v);
    l = __float2half(v - __half2float(h));
}

__device__ __forceinline__ void split2_store(__half* oh, __half* ol,
                                             size_t idx, float v0, float v1) {
    __half h0, l0, h1, l1;
    split1(v0, h0, l0); split1(v1, h1, l1);
    *reinterpret_cast<uint32_t*>(oh + idx) = packh(h0, h1);
    *reinterpret_cast<uint32_t*>(ol + idx) = packh(l0, l1);
}

// ---------------------------------------------------------------------------
// cp.async one K-chunk (32 fp16) of all 4 tiles into a stage, commit group.
// Stage bytes: A 2048 chunks of 16B, B 1024 chunks; 3072 total / 512 thr = 6.
// ---------------------------------------------------------------------------
__device__ __forceinline__ void issue_chunk(
    uint32_t smStage,
    const __half* __restrict__ Ah, const __half* __restrict__ Al,
    int lda, int rowBase,
    const __half* __restrict__ Bh, const __half* __restrict__ Bl,
    int ldb, int colBase, int k0)
{
    const int tid = threadIdx.x;
#pragma unroll
    for (int i = 0; i < 6; i++) {
        const int id = tid + 512 * i;      // 0..3071
        if (id < 2048) {                   // A region
            const int tile = id >> 10;     // 0: Ah, 1: Al
            const int row  = (id >> 2) & 255;
            const int cc   = id & 3;
            const __half* g = (tile ? Al : Ah) +
                              (size_t)(rowBase + row) * lda + k0 + cc * 8;
            cp16(smStage + (tile ? OFF_AL : OFF_AH) +
                 row * ROWB + SWZB(row, cc * 16), g);
        } else {                           // B region
            const int r2   = id - 2048;
            const int tile = r2 >> 9;      // 0: Bh, 1: Bl
            const int row  = (r2 >> 2) & 127;
            const int cc   = r2 & 3;
            const __half* g = (tile ? Bl : Bh) +
                              (size_t)(colBase + row) * ldb + k0 + cc * 8;
            cp16(smStage + (tile ? OFF_BL : OFF_BH) +
                 row * ROWB + SWZB(row, cc * 16), g);
        }
    }
    asm volatile("cp.async.commit_group;" ::: "memory");
}

// ---------------------------------------------------------------------------
// compute one stage: 2 k16-steps, 3 split terms. Warp tile 64x32.
// ---------------------------------------------------------------------------
__device__ __forceinline__ void compute_stage(uint32_t sst, int mW, int nW,
                                              int rIn, int cInB,
                                              float acc[4][4][4])
{
#pragma unroll
    for (int ks = 0; ks < 2; ks++) {
        const int cIn = cInB + ks * 32;
        uint32_t bh[2][4], bl[2][4];
#pragma unroll
        for (int p = 0; p < 2; p++) {
            const int row = nW + p * 16 + rIn;
            const uint32_t off = (uint32_t)(row * ROWB + SWZB(row, cIn));
            LDSM4(bh[p][0], bh[p][1], bh[p][2], bh[p][3], sst + OFF_BH + off);
            LDSM4(bl[p][0], bl[p][1], bl[p][2], bl[p][3], sst + OFF_BL + off);
        }
#pragma unroll
        for (int mt = 0; mt < 4; mt++) {
            const int row = mW + mt * 16 + rIn;
            const uint32_t off = (uint32_t)(row * ROWB + SWZB(row, cIn));
            uint32_t ah[4], al[4];
            LDSM4(ah[0], ah[1], ah[2], ah[3], sst + OFF_AH + off);
            LDSM4(al[0], al[1], al[2], al[3], sst + OFF_AL + off);
#pragma unroll
            for (int nt = 0; nt < 4; nt++) {
                const int p = nt >> 1, s = nt & 1;
                MMA16816(acc[mt][nt], ah[0], ah[1], ah[2], ah[3], bh[p][s], bh[p][s + 2]);
                MMA16816(acc[mt][nt], ah[0], ah[1], ah[2], ah[3], bl[p][s], bl[p][s + 2]);
                MMA16816(acc[mt][nt], al[0], al[1], al[2], al[3], bh[p][s], bh[p][s + 2]);
            }
        }
    }
}

// ---------------------------------------------------------------------------
// NT GEMM core: 256x128 tile, 4-stage ring, one barrier per stage.
// ---------------------------------------------------------------------------
__device__ __forceinline__ void gemm_core(
    const __half* __restrict__ Ah, const __half* __restrict__ Al,
    int lda, int rowBase,
    const __half* __restrict__ Bh, const __half* __restrict__ Bl,
    int ldb, int colBase,
    int Kdim, char* sm, float acc[4][4][4])
{
    const uint32_t smBase = smem_u32(sm);
    const int lane = threadIdx.x & 31;
    const int warp = threadIdx.x >> 5;          // 0..15
    const int mW = (warp >> 2) * 64, nW = (warp & 3) * 32;
    const int grp = lane >> 3;
    const int rIn = (grp & 1) * 8 + (lane & 7);
    const int cInB = (grp >> 1) * 16;

    const int NC = Kdim / BKH;
    issue_chunk(smBase,          Ah, Al, lda, rowBase, Bh, Bl, ldb, colBase, 0);
    issue_chunk(smBase + STAGEB, Ah, Al, lda, rowBase, Bh, Bl, ldb, colBase, BKH);

    int stage = 0;
    for (int c = 0; c < NC; c++) {
        if (c + 2 < NC) {
            const int s2 = (stage + 2) & 3;
            issue_chunk(smBase + s2 * STAGEB, Ah, Al, lda, rowBase,
                        Bh, Bl, ldb, colBase, (c + 2) * BKH);
        } else {
            asm volatile("cp.async.commit_group;" ::: "memory");
        }
        asm volatile("cp.async.wait_group 2;" ::: "memory");
        __syncthreads();
        compute_stage(smBase + stage * STAGEB, mW, nW, rIn, cInB, acc);
        stage = (stage + 1) & 3;
    }
}

// ---------------------------------------------------------------------------
// Kernel 0: fp32 -> fp16 hi/lo split
// ---------------------------------------------------------------------------
__global__ __launch_bounds__(256)
void split_k(const float* __restrict__ in, __half* __restrict__ oh,
             __half* __restrict__ ol, int n4)
{
    const int i = blockIdx.x * 256 + threadIdx.x;
    if (i >= n4) return;
    float4 v = reinterpret_cast<const float4*>(in)[i];
    __half h0, l0, h1, l1, h2, l2, h3, l3;
    split1(v.x, h0, l0); split1(v.y, h1, l1);
    split1(v.z, h2, l2); split1(v.w, h3, l3);
    reinterpret_cast<uint2*>(oh)[i] = make_uint2(packh(h0, h1), packh(h2, h3));
    reinterpret_cast<uint2*>(ol)[i] = make_uint2(packh(l0, l1), packh(l2, l3));
}

// ---------------------------------------------------------------------------
// Kernel 1: QKV projection (x @ W^T + b). z selects Q/K/V.
// ---------------------------------------------------------------------------
__global__ __launch_bounds__(NTHREADS, 1)
void qkv_k(const float* __restrict__ bq, const float* __restrict__ bk,
           const float* __restrict__ bv)
{
    extern __shared__ char sm[];
    const int which = blockIdx.z;
    const float* bias = (which == 0) ? bq : (which == 1) ? bk : bv;
    const __half* Wh = g_Wh + (size_t)which * EMBED * EMBED;
    const __half* Wl = g_Wl + (size_t)which * EMBED * EMBED;

    const int rowBase = blockIdx.y * BM;
    const int colBase = blockIdx.x * BN;

    float acc[4][4][4] = {};
    gemm_core(g_xh, g_xl, EMBED, rowBase, Wh, Wl, EMBED, colBase, EMBED, sm, acc);

    const int warp = threadIdx.x >> 5, lane = threadIdx.x & 31;
    const int mW = (warp >> 2) * 64, nW = (warp & 3) * 32;

    if (which < 2) {
        __half* oh = (which == 0) ? g_Qh : g_Kh;
        __half* ol = (which == 0) ? g_Ql : g_Kl;
#pragma unroll
        for (int mt = 0; mt < 4; mt++) {
#pragma unroll
            for (int nt = 0; nt < 4; nt++) {
                const int r0 = rowBase + mW + mt * 16 + (lane >> 2);
                const int c0 = colBase + nW + nt * 8 + 2 * (lane & 3);
                const float b0 = bias[c0], b1 = bias[c0 + 1];
                split2_store(oh, ol, (size_t)r0 * EMBED + c0,
                             acc[mt][nt][0] + b0, acc[mt][nt][1] + b1);
                split2_store(oh, ol, (size_t)(r0 + 8) * EMBED + c0,
                             acc[mt][nt][2] + b0, acc[mt][nt][3] + b1);
            }
        }
    } else {
        // V: transpose-stage in SMEM [e 128][s 256] pitch 264, then copy out
        __syncthreads();                     // all GEMM smem reads done
        __half* sh = reinterpret_cast<__half*>(sm);
        __half* sl = sh + 128 * 264;
#pragma unroll
        for (int mt = 0; mt < 4; mt++) {
#pragma unroll
            for (int nt = 0; nt < 4; nt++) {
                const int rr = mW + mt * 16 + (lane >> 2);   // s_rel
                const int cc = nW + nt * 8 + 2 * (lane & 3); // e_rel
                const float b0 = bias[colBase + cc], b1 = bias[colBase + cc + 1];
                float v00 = acc[mt][nt][0] + b0, v01 = acc[mt][nt][1] + b1;
                float v10 = acc[mt][nt][2] + b0, v11 = acc[mt][nt][3] + b1;
                __half h, l;
                split1(v00, h, l); sh[cc * 264 + rr] = h;           sl[cc * 264 + rr] = l;
                split1(v01, h, l); sh[(cc + 1) * 264 + rr] = h;     sl[(cc + 1) * 264 + rr] = l;
                split1(v10, h, l); sh[cc * 264 + rr + 8] = h;       sl[cc * 264 + rr + 8] = l;
                split1(v11, h, l); sh[(cc + 1) * 264 + rr + 8] = h; sl[(cc + 1) * 264 + rr + 8] = l;
            }
        }
        __syncthreads();
        const int b = rowBase >> 11;
        const int sBase = rowBase & (SEQ - 1);
        const int erow = threadIdx.x >> 2, q = threadIdx.x & 3;    // 128 rows x 4 quarters
        const uint32_t* srcH = reinterpret_cast<const uint32_t*>(sh + erow * 264 + q * 64);
        const uint32_t* srcL = reinterpret_cast<const uint32_t*>(sl + erow * 264 + q * 64);
        const size_t dstE = ((size_t)(b * EMBED + colBase + erow) * SEQ + sBase + q * 64) >> 1;
        uint32_t* dH = reinterpret_cast<uint32_t*>(g_Vth) + dstE;
        uint32_t* dL = reinterpret_cast<uint32_t*>(g_Vtl) + dstE;
#pragma unroll
        for (int i = 0; i < 32; i++) { dH[i] = srcH[i]; dL[i] = srcL[i]; }
    }
}

// ---------------------------------------------------------------------------
// Kernel 2: raw scores (causal tiles only): (Q.K^T)/32 + mask(-999)
// ---------------------------------------------------------------------------
__global__ __launch_bounds__(NTHREADS, 1)
void scores_k(float* __restrict__ wts)
{
    if ((int)blockIdx.x > 2 * (int)blockIdx.y + 1) return;  // fully masked
    extern __shared__ char sm[];
    const int b = blockIdx.z;
    const __half* Qh = g_Qh + (size_t)b * SEQ * EMBED;
    const __half* Ql = g_Ql + (size_t)b * SEQ * EMBED;
    const __half* Kh = g_Kh + (size_t)b * SEQ * EMBED;
    const __half* Kl = g_Kl + (size_t)b * SEQ * EMBED;
    float* S = wts + (size_t)b * SEQ * SEQ;

    const int rowBase = blockIdx.y * BM;
    const int colBase = blockIdx.x * BN;

    float acc[4][4][4] = {};
    gemm_core(Qh, Ql, EMBED, rowBase, Kh, Kl, EMBED, colBase, EMBED, sm, acc);

    const int warp = threadIdx.x >> 5, lane = threadIdx.x & 31;
    const int mW = (warp >> 2) * 64, nW = (warp & 3) * 32;
    const float scale = 0.03125f;

#pragma unroll
    for (int mt = 0; mt < 4; mt++) {
#pragma unroll
        for (int nt = 0; nt < 4; nt++) {
            const int q0 = rowBase + mW + mt * 16 + (lane >> 2);
            const int c0 = colBase + nW + nt * 8 + 2 * (lane & 3);
            float2 v0, v1;
            v0.x = acc[mt][nt][0] * scale + ((c0 + 0) > q0 ? -999.0f : 0.0f);
            v0.y = acc[mt][nt][1] * scale + ((c0 + 1) > q0 ? -999.0f : 0.0f);
            v1.x = acc[mt][nt][2] * scale + ((c0 + 0) > (q0 + 8) ? -999.0f : 0.0f);
            v1.y = acc[mt][nt][3] * scale + ((c0 + 1) > (q0 + 8) ? -999.0f : 0.0f);
            *(float2*)&S[(size_t)q0 * SEQ + c0]       = v0;
            *(float2*)&S[(size_t)(q0 + 8) * SEQ + c0] = v1;
        }
    }
}

// ---------------------------------------------------------------------------
// Kernel 3: softmax over valid prefix; emits fp32 wts + split fp16 w
// ---------------------------------------------------------------------------
__global__ __launch_bounds__(256)
void softmax_k(float* __restrict__ wts)
{
    const int row = blockIdx.x;            // b*SEQ + q
    const int q = row & (SEQ - 1);
    const int L = ((q >> 7) + 1) << 7;
    float* p = wts + (size_t)row * SEQ;
    __half* wh = g_wh + (size_t)row * SEQ;
    __half* wl = g_wl + (size_t)row * SEQ;
    const int t = threadIdx.x;
    __shared__ float red[8];

    float mx = -1e30f;
    for (int k = t; k < L; k += 256) mx = fmaxf(mx, p[k]);
#pragma unroll
    for (int o = 16; o > 0; o >>= 1) mx = fmaxf(mx, __shfl_xor_sync(0xffffffffu, mx, o));
    if ((t & 31) == 0) red[t >> 5] = mx;
    __syncthreads();
    float mxall = red[0];
#pragma unroll
    for (int i = 1; i < 8; i++) mxall = fmaxf(mxall, red[i]);
    __syncthreads();

    float v[8];
    float s = 0.0f;
    {
        int i = 0;
        for (int k = t; k < L; k += 256, i++) { v[i] = __expf(p[k] - mxall); s += v[i]; }
    }
#pragma unroll
    for (int o = 16; o > 0; o >>= 1) s += __shfl_xor_sync(0xffffffffu, s, o);
    if ((t & 31) == 0) red[t >> 5] = s;
    __syncthreads();
    float total = 0.0f;
#pragma unroll
    for (int i = 0; i < 8; i++) total += red[i];
    const float inv = 1.0f / total;

    {
        int i = 0;
        for (int k = t; k < L; k += 256, i++) {
            const float w = v[i] * inv;
            p[k] = w;
            __half h, l;
            split1(w, h, l);
            wh[k] = h; wl[k] = l;
        }
    }
    const __half z = __float2half(0.0f);
    for (int k = L + t; k < SEQ; k += 256) { p[k] = 0.0f; wh[k] = z; wl[k] = z; }
}

// ---------------------------------------------------------------------------
// Kernel 4: out = w @ V via split NT GEMM against Vt; K truncated causally
// ---------------------------------------------------------------------------
__global__ __launch_bounds__(NTHREADS, 1)
void av_k(float* __restrict__ out)
{
    extern __shared__ char sm[];
    const int b = blockIdx.z;
    const __half* Ah = g_wh + (size_t)b * SEQ * SEQ;
    const __half* Al = g_wl + (size_t)b * SEQ * SEQ;
    const __half* Bh = g_Vth + (size_t)b * EMBED * SEQ;
    const __half* Bl = g_Vtl + (size_t)b * EMBED * SEQ;
    float* C = out + (size_t)b * SEQ * EMBED;

    const int rowBase = blockIdx.y * BM;
    const int colBase = blockIdx.x * BN;
    const int Keff = rowBase + BM;        // causal truncation

    float acc[4][4][4] = {};
    gemm_core(Ah, Al, SEQ, rowBase, Bh, Bl, SEQ, colBase, Keff, sm, acc);

    const int warp = threadIdx.x >> 5, lane = threadIdx.x & 31;
    const int mW = (warp >> 2) * 64, nW = (warp & 3) * 32;

#pragma unroll
    for (int mt = 0; mt < 4; mt++) {
#pragma unroll
        for (int nt = 0; nt < 4; nt++) {
            const int r0 = rowBase + mW + mt * 16 + (lane >> 2);
            const int c0 = colBase + nW + nt * 8 + 2 * (lane & 3);
            *(float2*)&C[(size_t)r0 * EMBED + c0] =
                make_float2(acc[mt][nt][0], acc[mt][nt][1]);
            *(float2*)&C[(size_t)(r0 + 8) * EMBED + c0] =
                make_float2(acc[mt][nt][2], acc[mt][nt][3]);
        }
    }
}

// ---------------------------------------------------------------------------
extern "C" void kernel_launch(void* const* d_in, const int* in_sizes, int n_in,
                              void* d_out, int out_size)
{
    const float* x  = (const float*)d_in[0];
    const float* Wq = (const float*)d_in[1];
    const float* bq = (const float*)d_in[2];
    const float* Wk = (const float*)d_in[3];
    const float* bk = (const float*)d_in[4];
    const float* Wv = (const float*)d_in[5];
    const float* bv = (const float*)d_in[6];

    float* out = (float*)d_out;
    float* wts = out + (size_t)MTOT * EMBED;

    cudaFuncSetAttribute(qkv_k,    cudaFuncAttributeMaxDynamicSharedMemorySize, SMEM_DYN);
    cudaFuncSetAttribute(scores_k, cudaFuncAttributeMaxDynamicSharedMemorySize, SMEM_DYN);
    cudaFuncSetAttribute(av_k,     cudaFuncAttributeMaxDynamicSharedMemorySize, SMEM_DYN);

    __half *xh, *xl, *Wh, *Wl;
    cudaGetSymbolAddress((void**)&xh, g_xh);
    cudaGetSymbolAddress((void**)&xl, g_xl);
    cudaGetSymbolAddress((void**)&Wh, g_Wh);
    cudaGetSymbolAddress((void**)&Wl, g_Wl);

    const int nx4 = MTOT * EMBED / 4;
    const int nw4 = EMBED * EMBED / 4;
    split_k<<<(nx4 + 255) / 256, 256>>>(x, xh, xl, nx4);
    split_k<<<(nw4 + 255) / 256, 256>>>(Wq, Wh,               Wl,               nw4);
    split_k<<<(nw4 + 255) / 256, 256>>>(Wk, Wh + nw4 * 4,     Wl + nw4 * 4,     nw4);
    split_k<<<(nw4 + 255) / 256, 256>>>(Wv, Wh + 2 * nw4 * 4, Wl + 2 * nw4 * 4, nw4);

    qkv_k<<<dim3(EMBED / BN, MTOT / BM, 3), NTHREADS, SMEM_DYN>>>(bq, bk, bv);
    scores_k<<<dim3(SEQ / BN, SEQ / BM, BATCH), NTHREADS, SMEM_DYN>>>(wts);
    softmax_k<<<dim3(MTOT), dim3(256)>>>(wts);
    av_k<<<dim3(EMBED / BN, SEQ / BM, BATCH), NTHREADS, SMEM_DYN>>>(out);
}

// round 8
// speedup vs baseline: 1.0057x; 1.0057x over previous
#include <cuda_runtime.h>
#include <cuda_fp16.h>
#include <stdint.h>

#define EMBED 1024
#define BATCH 4
#define SEQ   2048
#define MTOT  (BATCH * SEQ)   // 8192

#define BM 256
#define BN 128
#define BKH 32                 // fp16 k elements per stage
#define NTHREADS 512

#define ROWB   64              // bytes per SMEM row (XOR swizzle, no pad)
#define TILEA  (256 * ROWB)    // 16384 B (A hi or lo)
#define TILEBB (128 * ROWB)    // 8192 B  (B hi or lo)
#define OFF_AH 0
#define OFF_AL TILEA
#define OFF_BH (2 * TILEA)
#define OFF_BL (2 * TILEA + TILEBB)
#define STAGEB (2 * TILEA + 2 * TILEBB)  // 49152
#define NSTAGE 4
#define SMEM_DYN (NSTAGE * STAGEB)       // 196608

#define SWZB(row, c) ((c) ^ ((((row) >> 1) & 3) << 4))

// ---------------- scratch (device globals; fp16 split operands) ------------
__device__ __align__(128) __half g_xh[(size_t)MTOT * EMBED];
__device__ __align__(128) __half g_xl[(size_t)MTOT * EMBED];
__device__ __align__(128) __half g_Wh[(size_t)3 * EMBED * EMBED];
__device__ __align__(128) __half g_Wl[(size_t)3 * EMBED * EMBED];
__device__ __align__(128) __half g_Qh[(size_t)MTOT * EMBED];
__device__ __align__(128) __half g_Ql[(size_t)MTOT * EMBED];
__device__ __align__(128) __half g_Kh[(size_t)MTOT * EMBED];
__device__ __align__(128) __half g_Kl[(size_t)MTOT * EMBED];
__device__ __align__(128) __half g_Vth[(size_t)BATCH * EMBED * SEQ]; // [b][e][s]
__device__ __align__(128) __half g_Vtl[(size_t)BATCH * EMBED * SEQ];
__device__ __align__(128) __half g_wh[(size_t)BATCH * SEQ * SEQ];    // [b][q][k]
__device__ __align__(128) __half g_wl[(size_t)BATCH * SEQ * SEQ];

// ---------------------------------------------------------------------------
__device__ __forceinline__ uint32_t smem_u32(const void* p) {
    uint32_t a;
    asm("{ .reg .u64 t; cvta.to.shared.u64 t, %1; cvt.u32.u64 %0, t; }"
        : "=r"(a) : "l"(p));
    return a;
}

__device__ __forceinline__ void cp16(uint32_t saddr, const void* g) {
    asm volatile("cp.async.cg.shared.global [%0], [%1], 16;"
                 :: "r"(saddr), "l"(g));
}

#define LDSM4(r0, r1, r2, r3, addr)                                          \
    asm volatile("ldmatrix.sync.aligned.m8n8.x4.shared.b16 {%0,%1,%2,%3}, [%4];" \
                 : "=r"(r0), "=r"(r1), "=r"(r2), "=r"(r3) : "r"(addr))

#define MMA16816(d, a0, a1, a2, a3, b0, b1)                                  \
    asm volatile("mma.sync.aligned.m16n8k16.row.col.f32.f16.f16.f32 "        \
                 "{%0,%1,%2,%3}, {%4,%5,%6,%7}, {%8,%9}, {%0,%1,%2,%3};"     \
                 : "+f"(d[0]), "+f"(d[1]), "+f"(d[2]), "+f"(d[3])            \
                 : "r"(a0), "r"(a1), "r"(a2), "r"(a3), "r"(b0), "r"(b1))

__device__ __forceinline__ uint32_t packh(__half a, __half b) {
    return (uint32_t)__half_as_ushort(a) | ((uint32_t)__half_as_ushort(b) << 16);
}

__device__ __forceinline__ void split1(float v, __half& h, __half& l) {
    h = __float2half(v);
    l = __float2half(v - __half2float(h));
}

__device__ __forceinline__ void split2_store(__half* oh, __half* ol,
                                             size_t idx, float v0, float v1) {
    __half h0, l0, h1, l1;
    split1(v0, h0, l0); split1(v1, h1, l1);
    *reinterpret_cast<uint32_t*>(oh + idx) = packh(h0, h1);
    *reinterpret_cast<uint32_t*>(ol + idx) = packh(l0, l1);
}

// ---------------------------------------------------------------------------
// cp.async one K-chunk (32 fp16) of all 4 tiles into a stage, commit group.
// Stage bytes: A 2048 chunks of 16B, B 1024 chunks; 3072 total / 512 thr = 6.
// ---------------------------------------------------------------------------
__device__ __forceinline__ void issue_chunk(
    uint32_t smStage,
    const __half* __restrict__ Ah, const __half* __restrict__ Al,
    int lda, int rowBase,
    const __half* __restrict__ Bh, const __half* __restrict__ Bl,
    int ldb, int colBase, int k0)
{
    const int tid = threadIdx.x;
#pragma unroll
    for (int i = 0; i < 6; i++) {
        const int id = tid + 512 * i;      // 0..3071
        if (id < 2048) {                   // A region
            const int tile = id >> 10;     // 0: Ah, 1: Al
            const int row  = (id >> 2) & 255;
            const int cc   = id & 3;
            const __half* g = (tile ? Al : Ah) +
                              (size_t)(rowBase + row) * lda + k0 + cc * 8;
            cp16(smStage + (tile ? OFF_AL : OFF_AH) +
                 row * ROWB + SWZB(row, cc * 16), g);
        } else {                           // B region
            const int r2   = id - 2048;
            const int tile = r2 >> 9;      // 0: Bh, 1: Bl
            const int row  = (r2 >> 2) & 127;
            const int cc   = r2 & 3;
            const __half* g = (tile ? Bl : Bh) +
                              (size_t)(colBase + row) * ldb + k0 + cc * 8;
            cp16(smStage + (tile ? OFF_BL : OFF_BH) +
                 row * ROWB + SWZB(row, cc * 16), g);
        }
    }
    asm volatile("cp.async.commit_group;" ::: "memory");
}

// ---------------------------------------------------------------------------
// compute one stage: 2 k16-steps, 3 split terms. Warp tile 64x32.
// ---------------------------------------------------------------------------
__device__ __forceinline__ void compute_stage(uint32_t sst, int mW, int nW,
                                              int rIn, int cInB,
                                              float acc[4][4][4])
{
#pragma unroll
    for (int ks = 0; ks < 2; ks++) {
        const int cIn = cInB + ks * 32;
        uint32_t bh[2][4], bl[2][4];
#pragma unroll
        for (int p = 0; p < 2; p++) {
            const int row = nW + p * 16 + rIn;
            const uint32_t off = (uint32_t)(row * ROWB + SWZB(row, cIn));
            LDSM4(bh[p][0], bh[p][1], bh[p][2], bh[p][3], sst + OFF_BH + off);
            LDSM4(bl[p][0], bl[p][1], bl[p][2], bl[p][3], sst + OFF_BL + off);
        }
#pragma unroll
        for (int mt = 0; mt < 4; mt++) {
            const int row = mW + mt * 16 + rIn;
            const uint32_t off = (uint32_t)(row * ROWB + SWZB(row, cIn));
            uint32_t ah[4], al[4];
            LDSM4(ah[0], ah[1], ah[2], ah[3], sst + OFF_AH + off);
            LDSM4(al[0], al[1], al[2], al[3], sst + OFF_AL + off);
#pragma unroll
            for (int nt = 0; nt < 4; nt++) {
                const int p = nt >> 1, s = nt & 1;
                MMA16816(acc[mt][nt], ah[0], ah[1], ah[2], ah[3], bh[p][s], bh[p][s + 2]);
                MMA16816(acc[mt][nt], ah[0], ah[1], ah[2], ah[3], bl[p][s], bl[p][s + 2]);
                MMA16816(acc[mt][nt], al[0], al[1], al[2], al[3], bh[p][s], bh[p][s + 2]);
            }
        }
    }
}

// ---------------------------------------------------------------------------
// NT GEMM core: 256x128 tile, 4-stage ring, one barrier per stage.
// ---------------------------------------------------------------------------
__device__ __forceinline__ void gemm_core(
    const __half* __restrict__ Ah, const __half* __restrict__ Al,
    int lda, int rowBase,
    const __half* __restrict__ Bh, const __half* __restrict__ Bl,
    int ldb, int colBase,
    int Kdim, char* sm, float acc[4][4][4])
{
    const uint32_t smBase = smem_u32(sm);
    const int lane = threadIdx.x & 31;
    const int warp = threadIdx.x >> 5;          // 0..15
    const int mW = (warp >> 2) * 64, nW = (warp & 3) * 32;
    const int grp = lane >> 3;
    const int rIn = (grp & 1) * 8 + (lane & 7);
    const int cInB = (grp >> 1) * 16;

    const int NC = Kdim / BKH;
    issue_chunk(smBase,          Ah, Al, lda, rowBase, Bh, Bl, ldb, colBase, 0);
    issue_chunk(smBase + STAGEB, Ah, Al, lda, rowBase, Bh, Bl, ldb, colBase, BKH);

    int stage = 0;
    for (int c = 0; c < NC; c++) {
        if (c + 2 < NC) {
            const int s2 = (stage + 2) & 3;
            issue_chunk(smBase + s2 * STAGEB, Ah, Al, lda, rowBase,
                        Bh, Bl, ldb, colBase, (c + 2) * BKH);
        } else {
            asm volatile("cp.async.commit_group;" ::: "memory");
        }
        asm volatile("cp.async.wait_group 2;" ::: "memory");
        __syncthreads();
        compute_stage(smBase + stage * STAGEB, mW, nW, rIn, cInB, acc);
        stage = (stage + 1) & 3;
    }
}

// ---------------------------------------------------------------------------
// Kernel 0: fp32 -> fp16 hi/lo split
// ---------------------------------------------------------------------------
__global__ __launch_bounds__(256)
void split_k(const float* __restrict__ in, __half* __restrict__ oh,
             __half* __restrict__ ol, int n4)
{
    const int i = blockIdx.x * 256 + threadIdx.x;
    if (i >= n4) return;
    float4 v = reinterpret_cast<const float4*>(in)[i];
    __half h0, l0, h1, l1, h2, l2, h3, l3;
    split1(v.x, h0, l0); split1(v.y, h1, l1);
    split1(v.z, h2, l2); split1(v.w, h3, l3);
    reinterpret_cast<uint2*>(oh)[i] = make_uint2(packh(h0, h1), packh(h2, h3));
    reinterpret_cast<uint2*>(ol)[i] = make_uint2(packh(l0, l1), packh(l2, l3));
}

// ---------------------------------------------------------------------------
// Kernel 1: QKV projection (x @ W^T + b). z selects Q/K/V.
// ---------------------------------------------------------------------------
__global__ __launch_bounds__(NTHREADS, 1)
void qkv_k(const float* __restrict__ bq, const float* __restrict__ bk,
           const float* __restrict__ bv)
{
    extern __shared__ char sm[];
    const int which = blockIdx.z;
    const float* bias = (which == 0) ? bq : (which == 1) ? bk : bv;
    const __half* Wh = g_Wh + (size_t)which * EMBED * EMBED;
    const __half* Wl = g_Wl + (size_t)which * EMBED * EMBED;

    const int rowBase = blockIdx.y * BM;
    const int colBase = blockIdx.x * BN;

    float acc[4][4][4] = {};
    gemm_core(g_xh, g_xl, EMBED, rowBase, Wh, Wl, EMBED, colBase, EMBED, sm, acc);

    const int warp = threadIdx.x >> 5, lane = threadIdx.x & 31;
    const int mW = (warp >> 2) * 64, nW = (warp & 3) * 32;

    if (which < 2) {
        __half* oh = (which == 0) ? g_Qh : g_Kh;
        __half* ol = (which == 0) ? g_Ql : g_Kl;
#pragma unroll
        for (int mt = 0; mt < 4; mt++) {
#pragma unroll
            for (int nt = 0; nt < 4; nt++) {
                const int r0 = rowBase + mW + mt * 16 + (lane >> 2);
                const int c0 = colBase + nW + nt * 8 + 2 * (lane & 3);
                const float b0 = bias[c0], b1 = bias[c0 + 1];
                split2_store(oh, ol, (size_t)r0 * EMBED + c0,
                             acc[mt][nt][0] + b0, acc[mt][nt][1] + b1);
                split2_store(oh, ol, (size_t)(r0 + 8) * EMBED + c0,
                             acc[mt][nt][2] + b0, acc[mt][nt][3] + b1);
            }
        }
    } else {
        // V: transpose-stage in SMEM [e 128][s 256] pitch 264, then copy out
        __syncthreads();                     // all GEMM smem reads done
        __half* sh = reinterpret_cast<__half*>(sm);
        __half* sl = sh + 128 * 264;
#pragma unroll
        for (int mt = 0; mt < 4; mt++) {
#pragma unroll
            for (int nt = 0; nt < 4; nt++) {
                const int rr = mW + mt * 16 + (lane >> 2);   // s_rel
                const int cc = nW + nt * 8 + 2 * (lane & 3); // e_rel
                const float b0 = bias[colBase + cc], b1 = bias[colBase + cc + 1];
                float v00 = acc[mt][nt][0] + b0, v01 = acc[mt][nt][1] + b1;
                float v10 = acc[mt][nt][2] + b0, v11 = acc[mt][nt][3] + b1;
                __half h, l;
                split1(v00, h, l); sh[cc * 264 + rr] = h;           sl[cc * 264 + rr] = l;
                split1(v01, h, l); sh[(cc + 1) * 264 + rr] = h;     sl[(cc + 1) * 264 + rr] = l;
                split1(v10, h, l); sh[cc * 264 + rr + 8] = h;       sl[cc * 264 + rr + 8] = l;
                split1(v11, h, l); sh[(cc + 1) * 264 + rr + 8] = h; sl[(cc + 1) * 264 + rr + 8] = l;
            }
        }
        __syncthreads();
        const int b = rowBase >> 11;
        const int sBase = rowBase & (SEQ - 1);
        const int erow = threadIdx.x >> 2, q = threadIdx.x & 3;    // 128 rows x 4 quarters
        const uint32_t* srcH = reinterpret_cast<const uint32_t*>(sh + erow * 264 + q * 64);
        const uint32_t* srcL = reinterpret_cast<const uint32_t*>(sl + erow * 264 + q * 64);
        const size_t dstE = ((size_t)(b * EMBED + colBase + erow) * SEQ + sBase + q * 64) >> 1;
        uint32_t* dH = reinterpret_cast<uint32_t*>(g_Vth) + dstE;
        uint32_t* dL = reinterpret_cast<uint32_t*>(g_Vtl) + dstE;
#pragma unroll
        for (int i = 0; i < 32; i++) { dH[i] = srcH[i]; dL[i] = srcL[i]; }
    }
}

// ---------------------------------------------------------------------------
// Kernel 2: raw scores (causal tiles only): (Q.K^T)/32 + mask(-999)
// ---------------------------------------------------------------------------
__global__ __launch_bounds__(NTHREADS, 1)
void scores_k(float* __restrict__ wts)
{
    if ((int)blockIdx.x > 2 * (int)blockIdx.y + 1) return;  // fully masked
    extern __shared__ char sm[];
    const int b = blockIdx.z;
    const __half* Qh = g_Qh + (size_t)b * SEQ * EMBED;
    const __half* Ql = g_Ql + (size_t)b * SEQ * EMBED;
    const __half* Kh = g_Kh + (size_t)b * SEQ * EMBED;
    const __half* Kl = g_Kl + (size_t)b * SEQ * EMBED;
    float* S = wts + (size_t)b * SEQ * SEQ;

    const int rowBase = blockIdx.y * BM;
    const int colBase = blockIdx.x * BN;

    float acc[4][4][4] = {};
    gemm_core(Qh, Ql, EMBED, rowBase, Kh, Kl, EMBED, colBase, EMBED, sm, acc);

    const int warp = threadIdx.x >> 5, lane = threadIdx.x & 31;
    const int mW = (warp >> 2) * 64, nW = (warp & 3) * 32;
    const float scale = 0.03125f;

#pragma unroll
    for (int mt = 0; mt < 4; mt++) {
#pragma unroll
        for (int nt = 0; nt < 4; nt++) {
            const int q0 = rowBase + mW + mt * 16 + (lane >> 2);
            const int c0 = colBase + nW + nt * 8 + 2 * (lane & 3);
            float2 v0, v1;
            v0.x = acc[mt][nt][0] * scale + ((c0 + 0) > q0 ? -999.0f : 0.0f);
            v0.y = acc[mt][nt][1] * scale + ((c0 + 1) > q0 ? -999.0f : 0.0f);
            v1.x = acc[mt][nt][2] * scale + ((c0 + 0) > (q0 + 8) ? -999.0f : 0.0f);
            v1.y = acc[mt][nt][3] * scale + ((c0 + 1) > (q0 + 8) ? -999.0f : 0.0f);
            *(float2*)&S[(size_t)q0 * SEQ + c0]       = v0;
            *(float2*)&S[(size_t)(q0 + 8) * SEQ + c0] = v1;
        }
    }
}

// ---------------------------------------------------------------------------
// Kernel 3: softmax over valid prefix; emits fp32 wts + split fp16 w
// ---------------------------------------------------------------------------
__global__ __launch_bounds__(256)
void softmax_k(float* __restrict__ wts)
{
    const int row = blockIdx.x;            // b*SEQ + q
    const int q = row & (SEQ - 1);
    const int L = ((q >> 7) + 1) << 7;
    float* p = wts + (size_t)row * SEQ;
    __half* wh = g_wh + (size_t)row * SEQ;
    __half* wl = g_wl + (size_t)row * SEQ;
    const int t = threadIdx.x;
    __shared__ float red[8];

    float mx = -1e30f;
    for (int k = t; k < L; k += 256) mx = fmaxf(mx, p[k]);
#pragma unroll
    for (int o = 16; o > 0; o >>= 1) mx = fmaxf(mx, __shfl_xor_sync(0xffffffffu, mx, o));
    if ((t & 31) == 0) red[t >> 5] = mx;
    __syncthreads();
    float mxall = red[0];
#pragma unroll
    for (int i = 1; i < 8; i++) mxall = fmaxf(mxall, red[i]);
    __syncthreads();

    float v[8];
    float s = 0.0f;
    {
        int i = 0;
        for (int k = t; k < L; k += 256, i++) { v[i] = __expf(p[k] - mxall); s += v[i]; }
    }
#pragma unroll
    for (int o = 16; o > 0; o >>= 1) s += __shfl_xor_sync(0xffffffffu, s, o);
    if ((t & 31) == 0) red[t >> 5] = s;
    __syncthreads();
    float total = 0.0f;
#pragma unroll
    for (int i = 0; i < 8; i++) total += red[i];
    const float inv = 1.0f / total;

    {
        int i = 0;
        for (int k = t; k < L; k += 256, i++) {
            const float w = v[i] * inv;
            p[k] = w;
            __half h, l;
            split1(w, h, l);
            wh[k] = h; wl[k] = l;
        }
    }
    const __half z = __float2half(0.0f);
    for (int k = L + t; k < SEQ; k += 256) { p[k] = 0.0f; wh[k] = z; wl[k] = z; }
}

// ---------------------------------------------------------------------------
// Kernel 4: out = w @ V via split NT GEMM against Vt; K truncated causally
// ---------------------------------------------------------------------------
__global__ __launch_bounds__(NTHREADS, 1)
void av_k(float* __restrict__ out)
{
    extern __shared__ char sm[];
    const int b = blockIdx.z;
    const __half* Ah = g_wh + (size_t)b * SEQ * SEQ;
    const __half* Al = g_wl + (size_t)b * SEQ * SEQ;
    const __half* Bh = g_Vth + (size_t)b * EMBED * SEQ;
    const __half* Bl = g_Vtl + (size_t)b * EMBED * SEQ;
    float* C = out + (size_t)b * SEQ * EMBED;

    const int rowBase = blockIdx.y * BM;
    const int colBase = blockIdx.x * BN;
    const int Keff = rowBase + BM;        // causal truncation

    float acc[4][4][4] = {};
    gemm_core(Ah, Al, SEQ, rowBase, Bh, Bl, SEQ, colBase, Keff, sm, acc);

    const int warp = threadIdx.x >> 5, lane = threadIdx.x & 31;
    const int mW = (warp >> 2) * 64, nW = (warp & 3) * 32;

#pragma unroll
    for (int mt = 0; mt < 4; mt++) {
#pragma unroll
        for (int nt = 0; nt < 4; nt++) {
            const int r0 = rowBase + mW + mt * 16 + (lane >> 2);
            const int c0 = colBase + nW + nt * 8 + 2 * (lane & 3);
            *(float2*)&C[(size_t)r0 * EMBED + c0] =
                make_float2(acc[mt][nt][0], acc[mt][nt][1]);
            *(float2*)&C[(size_t)(r0 + 8) * EMBED + c0] =
                make_float2(acc[mt][nt][2], acc[mt][nt][3]);
        }
    }
}

// ---------------------------------------------------------------------------
extern "C" void kernel_launch(void* const* d_in, const int* in_sizes, int n_in,
                              void* d_out, int out_size)
{
    const float* x  = (const float*)d_in[0];
    const float* Wq = (const float*)d_in[1];
    const float* bq = (const float*)d_in[2];
    const float* Wk = (const float*)d_in[3];
    const float* bk = (const float*)d_in[4];
    const float* Wv = (const float*)d_in[5];
    const float* bv = (const float*)d_in[6];

    float* out = (float*)d_out;
    float* wts = out + (size_t)MTOT * EMBED;

    cudaFuncSetAttribute(qkv_k,    cudaFuncAttributeMaxDynamicSharedMemorySize, SMEM_DYN);
    cudaFuncSetAttribute(scores_k, cudaFuncAttributeMaxDynamicSharedMemorySize, SMEM_DYN);
    cudaFuncSetAttribute(av_k,     cudaFuncAttributeMaxDynamicSharedMemorySize, SMEM_DYN);

    __half *xh, *xl, *Wh, *Wl;
    cudaGetSymbolAddress((void**)&xh, g_xh);
    cudaGetSymbolAddress((void**)&xl, g_xl);
    cudaGetSymbolAddress((void**)&Wh, g_Wh);
    cudaGetSymbolAddress((void**)&Wl, g_Wl);

    const int nx4 = MTOT * EMBED / 4;
    const int nw4 = EMBED * EMBED / 4;
    split_k<<<(nx4 + 255) / 256, 256>>>(x, xh, xl, nx4);
    split_k<<<(nw4 + 255) / 256, 256>>>(Wq, Wh,               Wl,               nw4);
    split_k<<<(nw4 + 255) / 256, 256>>>(Wk, Wh + nw4 * 4,     Wl + nw4 * 4,     nw4);
    split_k<<<(nw4 + 255) / 256, 256>>>(Wv, Wh + 2 * nw4 * 4, Wl + 2 * nw4 * 4, nw4);

    qkv_k<<<dim3(EMBED / BN, MTOT / BM, 3), NTHREADS, SMEM_DYN>>>(bq, bk, bv);
    scores_k<<<dim3(SEQ / BN, SEQ / BM, BATCH), NTHREADS, SMEM_DYN>>>(wts);
    softmax_k<<<dim3(MTOT), dim3(256)>>>(wts);
    av_k<<<dim3(EMBED / BN, SEQ / BM, BATCH), NTHREADS, SMEM_DYN>>>(out);
}

// round 9
// speedup vs baseline: 2.8921x; 2.8758x over previous
#include <cuda_runtime.h>
#include <cuda_fp16.h>
#include <stdint.h>

#define EMBED 1024
#define BATCH 4
#define SEQ   2048
#define MTOT  (BATCH * SEQ)   // 8192

#define BM 128
#define BN 128
#define BKH 32                 // fp16 k elements per stage
#define NTHREADS 256

#define ROWB   64              // bytes per SMEM row (XOR swizzle, no pad)
#define TILEB  (128 * ROWB)    // 8192 B per fp16 tile
#define STAGEB (2 * TILEB)     // 16384 B (A, B)
#define NSTAGE 4
#define SMEM_DYN (NSTAGE * STAGEB)  // 65536 B

#define SWZB(row, c) ((c) ^ ((((row) >> 1) & 3) << 4))

// ---------------- scratch (device globals; fp16 operands) ------------------
__device__ __align__(128) __half g_x [(size_t)MTOT * EMBED];
__device__ __align__(128) __half g_W [(size_t)3 * EMBED * EMBED];
__device__ __align__(128) __half g_Q [(size_t)MTOT * EMBED];
__device__ __align__(128) __half g_K [(size_t)MTOT * EMBED];
__device__ __align__(128) __half g_Vt[(size_t)BATCH * EMBED * SEQ];  // [b][e][s]
__device__ __align__(128) __half g_w [(size_t)BATCH * SEQ * SEQ];    // [b][q][k]

// ---------------------------------------------------------------------------
__device__ __forceinline__ uint32_t smem_u32(const void* p) {
    uint32_t a;
    asm("{ .reg .u64 t; cvta.to.shared.u64 t, %1; cvt.u32.u64 %0, t; }"
        : "=r"(a) : "l"(p));
    return a;
}

__device__ __forceinline__ void cp16(uint32_t saddr, const void* g) {
    asm volatile("cp.async.cg.shared.global [%0], [%1], 16;"
                 :: "r"(saddr), "l"(g));
}

#define LDSM4(r0, r1, r2, r3, addr)                                          \
    asm volatile("ldmatrix.sync.aligned.m8n8.x4.shared.b16 {%0,%1,%2,%3}, [%4];" \
                 : "=r"(r0), "=r"(r1), "=r"(r2), "=r"(r3) : "r"(addr))

#define MMA16816(d, a0, a1, a2, a3, b0, b1)                                  \
    asm volatile("mma.sync.aligned.m16n8k16.row.col.f32.f16.f16.f32 "        \
                 "{%0,%1,%2,%3}, {%4,%5,%6,%7}, {%8,%9}, {%0,%1,%2,%3};"     \
                 : "+f"(d[0]), "+f"(d[1]), "+f"(d[2]), "+f"(d[3])            \
                 : "r"(a0), "r"(a1), "r"(a2), "r"(a3), "r"(b0), "r"(b1))

__device__ __forceinline__ uint32_t packh(__half a, __half b) {
    return (uint32_t)__half_as_ushort(a) | ((uint32_t)__half_as_ushort(b) << 16);
}

// ---------------------------------------------------------------------------
// cp.async one K-chunk (32 fp16) of A and B tiles into a stage (1024 x 16B)
// ---------------------------------------------------------------------------
__device__ __forceinline__ void issue_chunk(
    uint32_t smStage,
    const __half* __restrict__ A, int lda, int rowBase,
    const __half* __restrict__ B, int ldb, int colBase, int k0)
{
    const int tid = threadIdx.x;
#pragma unroll
    for (int i = 0; i < 4; i++) {
        const int id   = tid + 256 * i;    // 0..1023
        const int tile = id >> 9;          // 0: A, 1: B
        const int row  = (id >> 2) & 127;
        const int cc   = id & 3;
        const __half* g = (tile ? B + (size_t)(colBase + row) * ldb
                                : A + (size_t)(rowBase + row) * lda) + k0 + cc * 8;
        cp16(smStage + tile * TILEB + row * ROWB + SWZB(row, cc * 16), g);
    }
    asm volatile("cp.async.commit_group;" ::: "memory");
}

// ---------------------------------------------------------------------------
// compute one stage: 2 k16-steps, single term. Warp tile 64x32.
// ---------------------------------------------------------------------------
__device__ __forceinline__ void compute_stage(uint32_t sst, int mW, int nW,
                                              int rIn, int cInB,
                                              float acc[4][4][4])
{
#pragma unroll
    for (int ks = 0; ks < 2; ks++) {
        const int cIn = cInB + ks * 32;
        uint32_t bh[2][4];
#pragma unroll
        for (int p = 0; p < 2; p++) {
            const int row = nW + p * 16 + rIn;
            const uint32_t off = (uint32_t)(row * ROWB + SWZB(row, cIn));
            LDSM4(bh[p][0], bh[p][1], bh[p][2], bh[p][3], sst + TILEB + off);
        }
#pragma unroll
        for (int mt = 0; mt < 4; mt++) {
            const int row = mW + mt * 16 + rIn;
            const uint32_t off = (uint32_t)(row * ROWB + SWZB(row, cIn));
            uint32_t ah[4];
            LDSM4(ah[0], ah[1], ah[2], ah[3], sst + off);
#pragma unroll
            for (int nt = 0; nt < 4; nt++) {
                const int p = nt >> 1, s = nt & 1;
                MMA16816(acc[mt][nt], ah[0], ah[1], ah[2], ah[3],
                         bh[p][s], bh[p][s + 2]);
            }
        }
    }
}

// ---------------------------------------------------------------------------
// NT GEMM core: 128x128 tile, 4-stage cp.async ring, one barrier per stage
// ---------------------------------------------------------------------------
__device__ __forceinline__ void gemm_core(
    const __half* __restrict__ A, int lda, int rowBase,
    const __half* __restrict__ B, int ldb, int colBase,
    int Kdim, char* sm, float acc[4][4][4])
{
    const uint32_t smBase = smem_u32(sm);
    const int lane = threadIdx.x & 31;
    const int warp = threadIdx.x >> 5;
    const int mW = (warp >> 2) * 64, nW = (warp & 3) * 32;
    const int grp = lane >> 3;
    const int rIn = (grp & 1) * 8 + (lane & 7);
    const int cInB = (grp >> 1) * 16;

    const int NC = Kdim / BKH;
    issue_chunk(smBase,          A, lda, rowBase, B, ldb, colBase, 0);
    issue_chunk(smBase + STAGEB, A, lda, rowBase, B, ldb, colBase, BKH);

    int stage = 0;
    for (int c = 0; c < NC; c++) {
        if (c + 2 < NC) {
            const int s2 = (stage + 2) & 3;
            issue_chunk(smBase + s2 * STAGEB, A, lda, rowBase,
                        B, ldb, colBase, (c + 2) * BKH);
        } else {
            asm volatile("cp.async.commit_group;" ::: "memory");
        }
        asm volatile("cp.async.wait_group 2;" ::: "memory");
        __syncthreads();
        compute_stage(smBase + stage * STAGEB, mW, nW, rIn, cInB, acc);
        stage = (stage + 1) & 3;
    }
}

// ---------------------------------------------------------------------------
// Kernel 0: fp32 -> fp16 convert
// ---------------------------------------------------------------------------
__global__ __launch_bounds__(256)
void conv_k(const float* __restrict__ in, __half* __restrict__ o, int n4)
{
    const int i = blockIdx.x * 256 + threadIdx.x;
    if (i >= n4) return;
    float4 v = reinterpret_cast<const float4*>(in)[i];
    reinterpret_cast<uint2*>(o)[i] =
        make_uint2(packh(__float2half(v.x), __float2half(v.y)),
                   packh(__float2half(v.z), __float2half(v.w)));
}

// ---------------------------------------------------------------------------
// Kernel 1: QKV projection (x @ W^T + b). z selects Q/K/V.
// V goes TRANSPOSED into g_Vt via SMEM staging.
// ---------------------------------------------------------------------------
__global__ __launch_bounds__(NTHREADS, 2)
void qkv_k(const float* __restrict__ bq, const float* __restrict__ bk,
           const float* __restrict__ bv)
{
    extern __shared__ char sm[];
    const int which = blockIdx.z;
    const float* bias = (which == 0) ? bq : (which == 1) ? bk : bv;
    const __half* W = g_W + (size_t)which * EMBED * EMBED;

    const int rowBase = blockIdx.y * BM;
    const int colBase = blockIdx.x * BN;

    float acc[4][4][4] = {};
    gemm_core(g_x, EMBED, rowBase, W, EMBED, colBase, EMBED, sm, acc);

    const int warp = threadIdx.x >> 5, lane = threadIdx.x & 31;
    const int mW = (warp >> 2) * 64, nW = (warp & 3) * 32;

    if (which < 2) {
        __half* o = (which == 0) ? g_Q : g_K;
#pragma unroll
        for (int mt = 0; mt < 4; mt++) {
#pragma unroll
            for (int nt = 0; nt < 4; nt++) {
                const int r0 = rowBase + mW + mt * 16 + (lane >> 2);
                const int c0 = colBase + nW + nt * 8 + 2 * (lane & 3);
                const float b0 = bias[c0], b1 = bias[c0 + 1];
                *reinterpret_cast<uint32_t*>(o + (size_t)r0 * EMBED + c0) =
                    packh(__float2half(acc[mt][nt][0] + b0),
                          __float2half(acc[mt][nt][1] + b1));
                *reinterpret_cast<uint32_t*>(o + (size_t)(r0 + 8) * EMBED + c0) =
                    packh(__float2half(acc[mt][nt][2] + b0),
                          __float2half(acc[mt][nt][3] + b1));
            }
        }
    } else {
        // V: transpose-stage in SMEM [e 128][s pitch 136], then coalesced out
        __syncthreads();
        __half* sh = reinterpret_cast<__half*>(sm);
#pragma unroll
        for (int mt = 0; mt < 4; mt++) {
#pragma unroll
            for (int nt = 0; nt < 4; nt++) {
                const int rr = mW + mt * 16 + (lane >> 2);   // s_rel
                const int cc = nW + nt * 8 + 2 * (lane & 3); // e_rel
                const float b0 = bias[colBase + cc], b1 = bias[colBase + cc + 1];
                sh[cc * 136 + rr]           = __float2half(acc[mt][nt][0] + b0);
                sh[(cc + 1) * 136 + rr]     = __float2half(acc[mt][nt][1] + b1);
                sh[cc * 136 + rr + 8]       = __float2half(acc[mt][nt][2] + b0);
                sh[(cc + 1) * 136 + rr + 8] = __float2half(acc[mt][nt][3] + b1);
            }
        }
        __syncthreads();
        const int b = rowBase >> 11;
        const int sBase = rowBase & (SEQ - 1);
        const int erow = threadIdx.x >> 1, half = threadIdx.x & 1;
        const uint32_t* src = reinterpret_cast<const uint32_t*>(sh + erow * 136 + half * 64);
        const size_t dstE = ((size_t)(b * EMBED + colBase + erow) * SEQ + sBase + half * 64) >> 1;
        uint32_t* d = reinterpret_cast<uint32_t*>(g_Vt) + dstE;
#pragma unroll
        for (int i = 0; i < 32; i++) d[i] = src[i];
    }
}

// ---------------------------------------------------------------------------
// Kernel 2: raw scores (lower-triangle tiles): (Q.K^T)/32 + mask(-999)
// ---------------------------------------------------------------------------
__global__ __launch_bounds__(NTHREADS, 2)
void scores_k(float* __restrict__ wts)
{
    if (blockIdx.x > blockIdx.y) return;
    extern __shared__ char sm[];
    const int b = blockIdx.z;
    const __half* Q = g_Q + (size_t)b * SEQ * EMBED;
    const __half* K = g_K + (size_t)b * SEQ * EMBED;
    float* S = wts + (size_t)b * SEQ * SEQ;

    const int rowBase = blockIdx.y * BM;
    const int colBase = blockIdx.x * BN;

    float acc[4][4][4] = {};
    gemm_core(Q, EMBED, rowBase, K, EMBED, colBase, EMBED, sm, acc);

    const int warp = threadIdx.x >> 5, lane = threadIdx.x & 31;
    const int mW = (warp >> 2) * 64, nW = (warp & 3) * 32;
    const float scale = 0.03125f;

#pragma unroll
    for (int mt = 0; mt < 4; mt++) {
#pragma unroll
        for (int nt = 0; nt < 4; nt++) {
            const int q0 = rowBase + mW + mt * 16 + (lane >> 2);
            const int c0 = colBase + nW + nt * 8 + 2 * (lane & 3);
            float2 v0, v1;
            v0.x = acc[mt][nt][0] * scale + ((c0 + 0) > q0 ? -999.0f : 0.0f);
            v0.y = acc[mt][nt][1] * scale + ((c0 + 1) > q0 ? -999.0f : 0.0f);
            v1.x = acc[mt][nt][2] * scale + ((c0 + 0) > (q0 + 8) ? -999.0f : 0.0f);
            v1.y = acc[mt][nt][3] * scale + ((c0 + 1) > (q0 + 8) ? -999.0f : 0.0f);
            *(float2*)&S[(size_t)q0 * SEQ + c0]       = v0;
            *(float2*)&S[(size_t)(q0 + 8) * SEQ + c0] = v1;
        }
    }
}

// ---------------------------------------------------------------------------
// Kernel 3: softmax over valid prefix; emits fp32 wts + fp16 w
// ---------------------------------------------------------------------------
__global__ __launch_bounds__(256)
void softmax_k(float* __restrict__ wts)
{
    const int row = blockIdx.x;            // b*SEQ + q
    const int q = row & (SEQ - 1);
    const int L = ((q >> 7) + 1) << 7;
    float* p = wts + (size_t)row * SEQ;
    __half* wh = g_w + (size_t)row * SEQ;
    const int t = threadIdx.x;
    __shared__ float red[8];

    float mx = -1e30f;
    for (int k = t; k < L; k += 256) mx = fmaxf(mx, p[k]);
#pragma unroll
    for (int o = 16; o > 0; o >>= 1) mx = fmaxf(mx, __shfl_xor_sync(0xffffffffu, mx, o));
    if ((t & 31) == 0) red[t >> 5] = mx;
    __syncthreads();
    float mxall = red[0];
#pragma unroll
    for (int i = 1; i < 8; i++) mxall = fmaxf(mxall, red[i]);
    __syncthreads();

    float v[8];
    float s = 0.0f;
    {
        int i = 0;
        for (int k = t; k < L; k += 256, i++) { v[i] = __expf(p[k] - mxall); s += v[i]; }
    }
#pragma unroll
    for (int o = 16; o > 0; o >>= 1) s += __shfl_xor_sync(0xffffffffu, s, o);
    if ((t & 31) == 0) red[t >> 5] = s;
    __syncthreads();
    float total = 0.0f;
#pragma unroll
    for (int i = 0; i < 8; i++) total += red[i];
    const float inv = 1.0f / total;

    {
        int i = 0;
        for (int k = t; k < L; k += 256, i++) {
            const float w = v[i] * inv;
            p[k] = w;
            wh[k] = __float2half(w);
        }
    }
    const __half z = __float2half(0.0f);
    for (int k = L + t; k < SEQ; k += 256) { p[k] = 0.0f; wh[k] = z; }
}

// ---------------------------------------------------------------------------
// Kernel 4: out = w @ V via NT GEMM against Vt; K truncated causally
// ---------------------------------------------------------------------------
__global__ __launch_bounds__(NTHREADS, 2)
void av_k(float* __restrict__ out)
{
    extern __shared__ char sm[];
    const int b = blockIdx.z;
    const __half* A  = g_w  + (size_t)b * SEQ * SEQ;
    const __half* Bv = g_Vt + (size_t)b * EMBED * SEQ;
    float* C = out + (size_t)b * SEQ * EMBED;

    const int rowBase = blockIdx.y * BM;
    const int colBase = blockIdx.x * BN;
    const int Keff = rowBase + BM;        // causal truncation

    float acc[4][4][4] = {};
    gemm_core(A, SEQ, rowBase, Bv, SEQ, colBase, Keff, sm, acc);

    const int warp = threadIdx.x >> 5, lane = threadIdx.x & 31;
    const int mW = (warp >> 2) * 64, nW = (warp & 3) * 32;

#pragma unroll
    for (int mt = 0; mt < 4; mt++) {
#pragma unroll
        for (int nt = 0; nt < 4; nt++) {
            const int r0 = rowBase + mW + mt * 16 + (lane >> 2);
            const int c0 = colBase + nW + nt * 8 + 2 * (lane & 3);
            *(float2*)&C[(size_t)r0 * EMBED + c0] =
                make_float2(acc[mt][nt][0], acc[mt][nt][1]);
            *(float2*)&C[(size_t)(r0 + 8) * EMBED + c0] =
                make_float2(acc[mt][nt][2], acc[mt][nt][3]);
        }
    }
}

// ---------------------------------------------------------------------------
extern "C" void kernel_launch(void* const* d_in, const int* in_sizes, int n_in,
                              void* d_out, int out_size)
{
    const float* x  = (const float*)d_in[0];
    const float* Wq = (const float*)d_in[1];
    const float* bq = (const float*)d_in[2];
    const float* Wk = (const float*)d_in[3];
    const float* bk = (const float*)d_in[4];
    const float* Wv = (const float*)d_in[5];
    const float* bv = (const float*)d_in[6];

    float* out = (float*)d_out;
    float* wts = out + (size_t)MTOT * EMBED;

    cudaFuncSetAttribute(qkv_k,    cudaFuncAttributeMaxDynamicSharedMemorySize, SMEM_DYN);
    cudaFuncSetAttribute(scores_k, cudaFuncAttributeMaxDynamicSharedMemorySize, SMEM_DYN);
    cudaFuncSetAttribute(av_k,     cudaFuncAttributeMaxDynamicSharedMemorySize, SMEM_DYN);

    __half *xh, *Wh;
    cudaGetSymbolAddress((void**)&xh, g_x);
    cudaGetSymbolAddress((void**)&Wh, g_W);

    const int nx4 = MTOT * EMBED / 4;
    const int nw4 = EMBED * EMBED / 4;
    conv_k<<<(nx4 + 255) / 256, 256>>>(x, xh, nx4);
    conv_k<<<(nw4 + 255) / 256, 256>>>(Wq, Wh,               nw4);
    conv_k<<<(nw4 + 255) / 256, 256>>>(Wk, Wh + nw4 * 4,     nw4);
    conv_k<<<(nw4 + 255) / 256, 256>>>(Wv, Wh + 2 * nw4 * 4, nw4);

    qkv_k<<<dim3(EMBED / BN, MTOT / BM, 3), NTHREADS, SMEM_DYN>>>(bq, bk, bv);
    scores_k<<<dim3(SEQ / BN, SEQ / BM, BATCH), NTHREADS, SMEM_DYN>>>(wts);
    softmax_k<<<dim3(MTOT), dim3(256)>>>(wts);
    av_k<<<dim3(EMBED / BN, SEQ / BM, BATCH), NTHREADS, SMEM_DYN>>>(out);
}